// round 15
// baseline (speedup 1.0000x reference)
#include <cuda_runtime.h>
#include <math.h>

#define BB   16
#define SS   128
#define TT   160
#define HH   512
#define EE   512
#define RDIM 128
#define GRID 148
#define NTH  1024
#define NWARP 32
#define TOTW (GRID * NWARP)   // 4736 warps

typedef unsigned long long ull;

// -------- device scratch (no allocations allowed) --------
__device__ __align__(16) float g_h[2][2][BB][HH];   // [parity][layer][b][k]
__device__ __align__(16) float g_c[2][2][BB][HH];
__device__ __align__(16) float g_part[2048][BB];    // full gate dots [gaterow][b]
__device__ ull      g_amax[SS][BB];
__device__ unsigned g_arrive;
__device__ int      g_mask_is_byte;

// -------- packed fp32x2 FMA (Blackwell) --------
static __device__ __forceinline__ ull ffma2(ull a, ull b, ull c) {
    ull d; asm("fma.rn.f32x2 %0, %1, %2, %3;" : "=l"(d) : "l"(a), "l"(b), "l"(c));
    return d;
}
static __device__ __forceinline__ float2 upk(ull v) {
    float2 r; asm("mov.b64 {%0, %1}, %2;" : "=f"(r.x), "=f"(r.y) : "l"(v));
    return r;
}
static __device__ __forceinline__ double sigd(double x) { return 1.0 / (1.0 + exp(-x)); }

// -------- software grid barrier (all 148 blocks resident: 1 block/SM) --------
static __device__ __forceinline__ void gsync() {
    __syncthreads();
    if (threadIdx.x == 0) {
        __threadfence();                       // fence.gpu: flush + L1 invalidate
        unsigned old  = atomicAdd(&g_arrive, 1u);
        unsigned need = (old / GRID + 1u) * GRID;
        while (*(volatile unsigned*)&g_arrive < need) { }
        __threadfence();
    }
    __syncthreads();
}

// ---------------------------------------------------------------------------
// Wavefront-exact GEMM tile: lane = r*8+kq (r=rows 0..3, kq=16B k-slice 0..7).
// Warp covers 8 rows (two quads) x 8 batches x full k.
// Per 128B k-chunk: 2 LDG.128 (each = 4 rows x full 128B line, nL=4, 4 wf)
//                 + 8 LDS.128 (kq-spread over all 32 banks, 1 wf each)
//                 + 32 ffma2  -> L1 wf (16) == fma cyc (16): balanced.
// acc[q][b] packs lane's (even,odd) k-slice partial as f32x2.
// ---------------------------------------------------------------------------
static __device__ __forceinline__ void gtileQ(const float* __restrict__ W, int wstride,
                                              int rowbase, int kw, int kx, int nc,
                                              const float* __restrict__ xs, int xst,
                                              ull accA[8], ull accB[8]) {
    int lane = threadIdx.x & 31;
    int r = lane >> 3, kq = lane & 7;
    const float* wrA = W + (size_t)(rowbase + r)     * wstride + kw + kq * 4;
    const float* wrB = W + (size_t)(rowbase + 4 + r) * wstride + kw + kq * 4;
    const float* xr  = xs + kx + kq * 4;
#pragma unroll 2
    for (int c = 0; c < nc; c++) {
        ulonglong2 wA = *(const ulonglong2*)(wrA + c * 32);
        ulonglong2 wB = *(const ulonglong2*)(wrB + c * 32);
#pragma unroll
        for (int b = 0; b < 8; b++) {
            ulonglong2 x = *(const ulonglong2*)(xr + b * xst + c * 32);
            accA[b] = ffma2(wA.x, x.x, accA[b]);
            accA[b] = ffma2(wA.y, x.y, accA[b]);
            accB[b] = ffma2(wB.x, x.x, accB[b]);
            accB[b] = ffma2(wB.y, x.y, accB[b]);
        }
    }
}

// Reduce one acc to the full dot (sum over kq octet); all lanes get the value.
static __device__ __forceinline__ float kqsum(ull a) {
    float2 f = upk(a);
    float s = f.x + f.y;
    s += __shfl_xor_sync(0xffffffffu, s, 1);
    s += __shfl_xor_sync(0xffffffffu, s, 2);
    s += __shfl_xor_sync(0xffffffffu, s, 4);
    return s;
}

// Store 8-row x 8-batch full gate dots (kq==0 lanes write).
static __device__ __forceinline__ void store_gates(int rowbase, int bq,
                                                   ull accA[8], ull accB[8]) {
    int lane = threadIdx.x & 31;
    int r = lane >> 3;
    float oa[8], ob[8];
#pragma unroll
    for (int b = 0; b < 8; b++) { oa[b] = kqsum(accA[b]); ob[b] = kqsum(accB[b]); }
    if ((lane & 7) == 0) {
        float4* dA = (float4*)&g_part[rowbase + r][bq * 8];
        float4* dB = (float4*)&g_part[rowbase + 4 + r][bq * 8];
        dA[0] = make_float4(oa[0], oa[1], oa[2], oa[3]);
        dA[1] = make_float4(oa[4], oa[5], oa[6], oa[7]);
        dB[0] = make_float4(ob[0], ob[1], ob[2], ob[3]);
        dB[1] = make_float4(ob[4], ob[5], ob[6], ob[7]);
    }
}

// Gate nonlinearities (fp64, fast-math-proof); cells spread across SMs.
static __device__ __forceinline__ void combine(int layer, int p,
                                               const float* __restrict__ bias) {
    int cell = blockIdx.x * 56 + threadIdx.x;
    if (threadIdx.x < 56 && cell < BB * HH) {
        int b = cell & 15, j = cell >> 4;
        float g0 = g_part[j][b]          + bias[j];
        float g1 = g_part[HH + j][b]     + bias[HH + j];
        float g2 = g_part[2 * HH + j][b] + bias[2 * HH + j];
        float g3 = g_part[3 * HH + j][b] + bias[3 * HH + j];
        double i_ = sigd((double)g0);
        double f_ = sigd((double)g1);
        double g_ = tanh((double)g2);
        double o_ = sigd((double)g3);
        float cold = g_c[p][layer][b][j];
        float cnew = (float)(f_ * (double)cold + i_ * g_);
        float hnew = (float)(o_ * tanh((double)cnew));
        g_c[p ^ 1][layer][b][j] = cnew;
        g_h[p ^ 1][layer][b][j] = hnew;
    }
}

// ---------------------------------------------------------------------------
__global__ void init_kernel(const float* __restrict__ hiddens,
                            const unsigned char* __restrict__ tmask) {
    int tid = threadIdx.x;
    if (tid == 0) g_arrive = 0u;
    for (int i = tid; i < SS * BB; i += blockDim.x) ((ull*)g_amax)[i] = 0ull;
    float* hf = &g_h[0][0][0][0];
    float* cf = &g_c[0][0][0][0];
    for (int i = tid; i < BB * HH; i += blockDim.x) {
        float v = hiddens[i];
        hf[i] = v; hf[BB * HH + i] = v;
        cf[i] = v; cf[BB * HH + i] = v;
    }
    __shared__ int sflag;
    if (tid == 0) sflag = 0;
    __syncthreads();
    int f = 0;   // int32 0/1 has zero bytes at i%4!=0; bool8 does not
    for (int i = tid; i < BB * SS; i += blockDim.x)
        if ((i & 3) && tmask[i]) f = 1;
    if (f) atomicOr(&sflag, 1);
    __syncthreads();
    if (tid == 0) g_mask_is_byte = sflag;
}

// ---------------------------------------------------------------------------
// Persistent kernel: 128-step recurrence + finalize. 5 grid barriers/step.
// ---------------------------------------------------------------------------
extern "C" __global__ void __launch_bounds__(NTH, 1)
seq_kernel(const float* __restrict__ sentences, const int* __restrict__ relations,
           const int* __restrict__ gold, const unsigned char* __restrict__ tmask,
           const float* __restrict__ embed, const float* __restrict__ rel_emb,
           const float* __restrict__ w_ih0, const float* __restrict__ w_hh0,
           const float* __restrict__ b0,
           const float* __restrict__ w_ih1, const float* __restrict__ w_hh1,
           const float* __restrict__ b1,
           const float* __restrict__ out_w, const float* __restrict__ out_b,
           const float* __restrict__ transfer_w, float* __restrict__ out) {
    extern __shared__ float xs[];        // [16][1152] max (x tiles, block-local)
    __shared__ int sidx[32];             // [0:16) widx, [16:32) rel
    __shared__ ull sbest[16];
    int tid = threadIdx.x, blk = blockIdx.x;
    int warp = tid >> 5, lane = tid & 31;
    int wid2 = warp * GRID + blk;        // SM-spread global warp id

    for (int t = 0; t < SS; t++) {
        int p = t & 1;
        // ---- phase A: x0 = [rel(128) | word(512) | h0_prev(512)], lstm0 dots ----
        if (tid < BB) {
            int b = tid, widx;
            if (t == 0) widx = 1;        // SOS / null token
            else {
                int m = g_mask_is_byte ? tmask[b * SS + t]
                                       : ((const int*)tmask)[b * SS + t];
                widx = m ? gold[b * SS + t - 1]
                         : (int)(0xFFFFFFFFu - (unsigned)(g_amax[t - 1][b] & 0xFFFFFFFFull));
            }
            sidx[b] = widx;
            sidx[16 + b] = relations[b * SS + t];
        }
        __syncthreads();
        for (int i = tid; i < BB * 288; i += NTH) {
            int b = i / 288, k4 = (i - b * 288) * 4;
            float4 v;
            if (k4 < RDIM)
                v = *(const float4*)(rel_emb + (size_t)sidx[16 + b] * RDIM + k4);
            else if (k4 < RDIM + EE)
                v = *(const float4*)(embed + (size_t)sidx[b] * EE + (k4 - RDIM));
            else
                v = *(const float4*)(&g_h[p][0][b][k4 - (RDIM + EE)]);
            *(float4*)(xs + b * 1152 + k4) = v;
        }
        __syncthreads();
        if (wid2 < 512) {                // 256 rowgroups(8) x 2 batch-halves
            int rq = wid2 >> 1, bq = wid2 & 1;
            int rowbase = rq * 8;
            ull accA[8], accB[8];
#pragma unroll
            for (int b = 0; b < 8; b++) { accA[b] = 0ull; accB[b] = 0ull; }
            const float* xb = xs + bq * 8 * 1152;
            gtileQ(w_ih0, RDIM + EE, rowbase, 0, 0,   20, xb, 1152, accA, accB);
            gtileQ(w_hh0, HH,        rowbase, 0, 640, 16, xb, 1152, accA, accB);
            store_gates(rowbase, bq, accA, accB);
        }
        gsync();
        combine(0, p, b0);
        gsync();
        // ---- phase B: x1 = [h0_new(512) | h1_prev(512)], lstm1 dots ----
        for (int i = tid; i < BB * 256; i += NTH) {
            int b = i >> 8, k4 = (i & 255) * 4;
            float4 v = (k4 < HH) ? *(const float4*)(&g_h[p ^ 1][0][b][k4])
                                 : *(const float4*)(&g_h[p][1][b][k4 - HH]);
            *(float4*)(xs + b * 1024 + k4) = v;
        }
        __syncthreads();
        if (wid2 < 512) {
            int rq = wid2 >> 1, bq = wid2 & 1;
            int rowbase = rq * 8;
            ull accA[8], accB[8];
#pragma unroll
            for (int b = 0; b < 8; b++) { accA[b] = 0ull; accB[b] = 0ull; }
            const float* xb = xs + bq * 8 * 1024;
            gtileQ(w_ih1, HH, rowbase, 0, 0,   16, xb, 1024, accA, accB);
            gtileQ(w_hh1, HH, rowbase, 0, 512, 16, xb, 1024, accA, accB);
            store_gates(rowbase, bq, accA, accB);
        }
        gsync();
        combine(1, p, b1);
        gsync();
        // ---- phase C: outproj (8000 tasks: 8 rows x 8 batches) + argmax ----
        if (tid < 16) sbest[tid] = 0ull;
        for (int i = tid; i < BB * 128; i += NTH) {
            int b = i >> 7, k4 = (i & 127) * 4;
            *(float4*)(xs + b * 512 + k4) = *(const float4*)(&g_h[p ^ 1][1][b][k4]);
        }
        __syncthreads();
        for (int tk = wid2; tk < 8000; tk += TOTW) {
            int rq = tk >> 1, bq = tk & 1;
            int rowbase = rq * 8;
            int r = lane >> 3;
            int rowA = rowbase + r, rowB = rowbase + 4 + r;
            ull accA[8], accB[8];
#pragma unroll
            for (int b = 0; b < 8; b++) { accA[b] = 0ull; accB[b] = 0ull; }
            gtileQ(out_w, HH, rowbase, 0, 0, 16, xs + bq * 8 * 512, 512, accA, accB);
            float biasA = out_b[rowA], biasB = out_b[rowB];
            ull my = 0ull;
#pragma unroll
            for (int b = 0; b < 8; b++) {
                float sA = kqsum(accA[b]) + biasA;
                float sB = kqsum(accB[b]) + biasB;
                unsigned uA = __float_as_uint(sA);
                uA = (uA & 0x80000000u) ? ~uA : (uA | 0x80000000u);
                unsigned uB = __float_as_uint(sB);
                uB = (uB & 0x80000000u) ? ~uB : (uB | 0x80000000u);
                ull kA = ((ull)uA << 32) | (ull)(0xFFFFFFFFu - (unsigned)rowA);
                ull kB = ((ull)uB << 32) | (ull)(0xFFFFFFFFu - (unsigned)rowB);
                ull key = (kB > kA) ? kB : kA;
#pragma unroll
                for (int off = 8; off <= 16; off <<= 1) {  // max over r quads
                    ull o2 = __shfl_xor_sync(0xffffffffu, key, off);
                    if (o2 > key) key = o2;
                }
                if (lane == bq * 8 + b) my = key;          // lane gb keeps its batch
            }
            if (lane < 16 && my) atomicMax(&sbest[lane], my);
        }
        __syncthreads();
        if (tid < 16) atomicMax(&g_amax[t][tid], sbest[tid]);
        gsync();
    }

    // ---- finalize: out[b,t,:] = transfer_w[argmax] for t<128, else sentences ----
    for (int i = blk * NTH + tid; i < BB * TT * (EE / 4); i += GRID * NTH) {
        int k4 = (i & 127) * 4;
        int bt = i >> 7;
        int b = bt / TT, tt = bt - b * TT;
        float4 v;
        if (tt < SS) {
            int idx = (int)(0xFFFFFFFFu - (unsigned)(g_amax[tt][b] & 0xFFFFFFFFull));
            v = *(const float4*)(transfer_w + (size_t)idx * EE + k4);
        } else {
            v = *(const float4*)(sentences + (size_t)bt * EE + k4);
        }
        *(float4*)(out + (size_t)bt * EE + k4) = v;
    }
}

// ---------------------------------------------------------------------------
extern "C" void kernel_launch(void* const* d_in, const int* in_sizes, int n_in,
                              void* d_out, int out_size) {
    const float* hiddens    = (const float*)d_in[0];
    const float* sentences  = (const float*)d_in[1];
    const int*   relations  = (const int*)d_in[2];
    const int*   gold       = (const int*)d_in[3];
    const unsigned char* tmask = (const unsigned char*)d_in[4];
    const float* embed      = (const float*)d_in[5];
    const float* rel_emb    = (const float*)d_in[6];
    const float* w_ih0      = (const float*)d_in[7];
    const float* w_hh0      = (const float*)d_in[8];
    const float* b0         = (const float*)d_in[9];
    const float* w_ih1      = (const float*)d_in[10];
    const float* w_hh1      = (const float*)d_in[11];
    const float* b1         = (const float*)d_in[12];
    const float* out_w      = (const float*)d_in[13];
    const float* out_b      = (const float*)d_in[14];
    const float* transfer_w = (const float*)d_in[15];

    const int smem = BB * 1152 * sizeof(float);   // 73728 B dynamic
    cudaFuncSetAttribute(seq_kernel, cudaFuncAttributeMaxDynamicSharedMemorySize, smem);

    init_kernel<<<1, 1024>>>(hiddens, tmask);
    seq_kernel<<<GRID, NTH, smem>>>(sentences, relations, gold, tmask, embed, rel_emb,
                                    w_ih0, w_hh0, b0, w_ih1, w_hh1, b1,
                                    out_w, out_b, transfer_w, (float*)d_out);
}

// round 16
// speedup vs baseline: 1.3225x; 1.3225x over previous
#include <cuda_runtime.h>
#include <math.h>

#define BB   16
#define SS   128
#define TT   160
#define HH   512
#define EE   512
#define RDIM 128
#define GRID 148
#define NTH  512
#define NWARP 16
#define TOTW (GRID * NWARP)   // 2368 warps

typedef unsigned long long ull;

// -------- device scratch (no allocations allowed) --------
__device__ __align__(16) float g_h[2][2][BB][HH];   // [parity][layer][b][k]
__device__ __align__(16) float g_c[2][2][BB][HH];
__device__ __align__(16) float g_part[8][2048][BB]; // gate slab partials
__device__ ull      g_amax[SS][BB];
__device__ unsigned g_arrive;
__device__ int      g_mask_is_byte;

// -------- packed fp32x2 FMA (Blackwell) --------
static __device__ __forceinline__ ull ffma2(ull a, ull b, ull c) {
    ull d; asm("fma.rn.f32x2 %0, %1, %2, %3;" : "=l"(d) : "l"(a), "l"(b), "l"(c));
    return d;
}
static __device__ __forceinline__ float2 upk(ull v) {
    float2 r; asm("mov.b64 {%0, %1}, %2;" : "=f"(r.x), "=f"(r.y) : "l"(v));
    return r;
}
static __device__ __forceinline__ double sigd(double x) { return 1.0 / (1.0 + exp(-x)); }

// -------- software grid barrier (all 148 blocks resident: 1 block/SM) --------
static __device__ __forceinline__ void gsync() {
    __syncthreads();
    if (threadIdx.x == 0) {
        __threadfence();
        unsigned old  = atomicAdd(&g_arrive, 1u);
        unsigned need = (old / GRID + 1u) * GRID;
        while (*(volatile unsigned*)&g_arrive < need) { }
        __threadfence();
    }
    __syncthreads();
}

// ---------------------------------------------------------------------------
// 8-rows x 16-batch tile, 128B k-chunks. lane = r*8+kq (r=0..3, kq=0..7).
// Per chunk: 2 LDG.128 (4 rows x full 128B line each -> 4 wf, no waste)
//          + 16 LDS.128 (kq-spread, all 32 banks, 4-lane broadcast -> 1 wf)
//          + 64 ffma2  => fma-bound (32 SM-cyc fma vs 24 L1-cyc).
// accA/accB: per-lane k-slice partials for rows (rowbase+r) / (rowbase+4+r).
// ---------------------------------------------------------------------------
static __device__ __forceinline__ void gtileQ(const float* __restrict__ W, int wstride,
                                              int rowbase, int kw, int kx, int nc,
                                              const float* __restrict__ xs, int xst,
                                              ull accA[16], ull accB[16]) {
    int lane = threadIdx.x & 31;
    int r = lane >> 3, kq = lane & 7;
    const float* wrA = W + (size_t)(rowbase + r)     * wstride + kw + kq * 4;
    const float* wrB = W + (size_t)(rowbase + 4 + r) * wstride + kw + kq * 4;
    const float* xr  = xs + kx + kq * 4;
#pragma unroll 2
    for (int c = 0; c < nc; c++) {
        ulonglong2 wA = *(const ulonglong2*)(wrA + c * 32);
        ulonglong2 wB = *(const ulonglong2*)(wrB + c * 32);
#pragma unroll
        for (int b = 0; b < 16; b++) {
            ulonglong2 x = *(const ulonglong2*)(xr + b * xst + c * 32);
            accA[b] = ffma2(wA.x, x.x, accA[b]);
            accA[b] = ffma2(wA.y, x.y, accA[b]);
            accB[b] = ffma2(wB.x, x.x, accB[b]);
            accB[b] = ffma2(wB.y, x.y, accB[b]);
        }
    }
}

// Sum a packed acc over the 8-kq octet; all lanes in the octet get the value.
static __device__ __forceinline__ float kqsum(ull a) {
    float2 f = upk(a);
    float s = f.x + f.y;
    s += __shfl_xor_sync(0xffffffffu, s, 1);
    s += __shfl_xor_sync(0xffffffffu, s, 2);
    s += __shfl_xor_sync(0xffffffffu, s, 4);
    return s;
}

// Store 8 rows x 16 batches of slab partials (kq==0 lanes write).
static __device__ __forceinline__ void store_gates(int slab, int rowbase,
                                                   ull accA[16], ull accB[16]) {
    int lane = threadIdx.x & 31;
    int r = lane >> 3;
    float oa[16], ob[16];
#pragma unroll
    for (int b = 0; b < 16; b++) { oa[b] = kqsum(accA[b]); ob[b] = kqsum(accB[b]); }
    if ((lane & 7) == 0) {
        float4* dA = (float4*)&g_part[slab][rowbase + r][0];
        float4* dB = (float4*)&g_part[slab][rowbase + 4 + r][0];
#pragma unroll
        for (int q = 0; q < 4; q++) {
            dA[q] = make_float4(oa[4*q], oa[4*q+1], oa[4*q+2], oa[4*q+3]);
            dB[q] = make_float4(ob[4*q], ob[4*q+1], ob[4*q+2], ob[4*q+3]);
        }
    }
}

// Gate combine (8 slabs, fixed order) + fp64 nonlinearities; spread across SMs.
static __device__ __forceinline__ void combine(int layer, int p,
                                               const float* __restrict__ bias) {
    int cell = blockIdx.x * 56 + threadIdx.x;
    if (threadIdx.x < 56 && cell < BB * HH) {
        int b = cell & 15, j = cell >> 4;
        float gs[4];
#pragma unroll
        for (int gi = 0; gi < 4; gi++) {
            float s = bias[gi * HH + j];
#pragma unroll
            for (int sl = 0; sl < 8; sl++) s += g_part[sl][gi * HH + j][b];
            gs[gi] = s;
        }
        double i_ = sigd((double)gs[0]);
        double f_ = sigd((double)gs[1]);
        double g_ = tanh((double)gs[2]);
        double o_ = sigd((double)gs[3]);
        float cold = g_c[p][layer][b][j];
        float cnew = (float)(f_ * (double)cold + i_ * g_);
        float hnew = (float)(o_ * tanh((double)cnew));
        g_c[p ^ 1][layer][b][j] = cnew;
        g_h[p ^ 1][layer][b][j] = hnew;
    }
}

// ---------------------------------------------------------------------------
__global__ void init_kernel(const float* __restrict__ hiddens,
                            const unsigned char* __restrict__ tmask) {
    int tid = threadIdx.x;
    if (tid == 0) g_arrive = 0u;
    for (int i = tid; i < SS * BB; i += blockDim.x) ((ull*)g_amax)[i] = 0ull;
    float* hf = &g_h[0][0][0][0];
    float* cf = &g_c[0][0][0][0];
    for (int i = tid; i < BB * HH; i += blockDim.x) {
        float v = hiddens[i];
        hf[i] = v; hf[BB * HH + i] = v;
        cf[i] = v; cf[BB * HH + i] = v;
    }
    __shared__ int sflag;
    if (tid == 0) sflag = 0;
    __syncthreads();
    int f = 0;   // int32 0/1 has zero bytes at i%4!=0; bool8 does not
    for (int i = tid; i < BB * SS; i += blockDim.x)
        if ((i & 3) && tmask[i]) f = 1;
    if (f) atomicOr(&sflag, 1);
    __syncthreads();
    if (tid == 0) g_mask_is_byte = sflag;
}

// ---------------------------------------------------------------------------
// Persistent kernel: 128-step recurrence + finalize. 5 grid barriers/step.
// 512 threads -> 128 regs/thread: accA/accB (64 regs) fit WITHOUT spilling.
// ---------------------------------------------------------------------------
extern "C" __global__ void __launch_bounds__(NTH, 1)
seq_kernel(const float* __restrict__ sentences, const int* __restrict__ relations,
           const int* __restrict__ gold, const unsigned char* __restrict__ tmask,
           const float* __restrict__ embed, const float* __restrict__ rel_emb,
           const float* __restrict__ w_ih0, const float* __restrict__ w_hh0,
           const float* __restrict__ b0,
           const float* __restrict__ w_ih1, const float* __restrict__ w_hh1,
           const float* __restrict__ b1,
           const float* __restrict__ out_w, const float* __restrict__ out_b,
           const float* __restrict__ transfer_w, float* __restrict__ out) {
    extern __shared__ float xs[];        // [16][1152] max (x tiles, block-local)
    __shared__ int sidx[32];             // [0:16) widx, [16:32) rel
    __shared__ ull sbest[16];
    int tid = threadIdx.x, blk = blockIdx.x;
    int warp = tid >> 5, lane = tid & 31;
    int wid2 = warp * GRID + blk;        // SM-spread global warp id

    for (int t = 0; t < SS; t++) {
        int p = t & 1;
        // ---- phase A: x0 = [rel(128) | word(512) | h0_prev(512)], lstm0 dots ----
        if (tid < BB) {
            int b = tid, widx;
            if (t == 0) widx = 1;        // SOS / null token
            else {
                int m = g_mask_is_byte ? tmask[b * SS + t]
                                       : ((const int*)tmask)[b * SS + t];
                widx = m ? gold[b * SS + t - 1]
                         : (int)(0xFFFFFFFFu - (unsigned)(g_amax[t - 1][b] & 0xFFFFFFFFull));
            }
            sidx[b] = widx;
            sidx[16 + b] = relations[b * SS + t];
        }
        __syncthreads();
        for (int i = tid; i < BB * 288; i += NTH) {
            int b = i / 288, k4 = (i - b * 288) * 4;
            float4 v;
            if (k4 < RDIM)
                v = *(const float4*)(rel_emb + (size_t)sidx[16 + b] * RDIM + k4);
            else if (k4 < RDIM + EE)
                v = *(const float4*)(embed + (size_t)sidx[b] * EE + (k4 - RDIM));
            else
                v = *(const float4*)(&g_h[p][0][b][k4 - (RDIM + EE)]);
            *(float4*)(xs + b * 1152 + k4) = v;
        }
        __syncthreads();
        if (wid2 < 2048) {               // 256 rowgroups(8 rows) x 8 k-slabs
            int rg = wid2 >> 3, slab = wid2 & 7;
            int rowbase = rg * 8;
            ull accA[16], accB[16];
#pragma unroll
            for (int b = 0; b < 16; b++) { accA[b] = 0ull; accB[b] = 0ull; }
            // slabs 0-3: w_ih0 (k 0..640 in 4x5 chunks); 4-7: w_hh0 (4x4 chunks)
            if (slab < 4)
                gtileQ(w_ih0, RDIM + EE, rowbase, slab * 160, slab * 160, 5,
                       xs, 1152, accA, accB);
            else
                gtileQ(w_hh0, HH, rowbase, (slab - 4) * 128, 640 + (slab - 4) * 128, 4,
                       xs, 1152, accA, accB);
            store_gates(slab, rowbase, accA, accB);
        }
        gsync();
        combine(0, p, b0);
        gsync();
        // ---- phase B: x1 = [h0_new(512) | h1_prev(512)], lstm1 dots ----
        for (int i = tid; i < BB * 256; i += NTH) {
            int b = i >> 8, k4 = (i & 255) * 4;
            float4 v = (k4 < HH) ? *(const float4*)(&g_h[p ^ 1][0][b][k4])
                                 : *(const float4*)(&g_h[p][1][b][k4 - HH]);
            *(float4*)(xs + b * 1024 + k4) = v;
        }
        __syncthreads();
        if (wid2 < 2048) {
            int rg = wid2 >> 3, slab = wid2 & 7;
            int rowbase = rg * 8;
            ull accA[16], accB[16];
#pragma unroll
            for (int b = 0; b < 16; b++) { accA[b] = 0ull; accB[b] = 0ull; }
            if (slab < 4)
                gtileQ(w_ih1, HH, rowbase, slab * 128, slab * 128, 4,
                       xs, 1024, accA, accB);
            else
                gtileQ(w_hh1, HH, rowbase, (slab - 4) * 128, 512 + (slab - 4) * 128, 4,
                       xs, 1024, accA, accB);
            store_gates(slab, rowbase, accA, accB);
        }
        gsync();
        combine(1, p, b1);
        gsync();
        // ---- phase C: outproj (4000 tasks: 8 rows x 16 batches) + argmax ----
        if (tid < 16) sbest[tid] = 0ull;
        for (int i = tid; i < BB * 128; i += NTH) {
            int b = i >> 7, k4 = (i & 127) * 4;
            *(float4*)(xs + b * 512 + k4) = *(const float4*)(&g_h[p ^ 1][1][b][k4]);
        }
        __syncthreads();
        for (int tk = wid2; tk < 4000; tk += TOTW) {
            int rowbase = tk * 8;
            int r = lane >> 3;
            int rowA = rowbase + r, rowB = rowbase + 4 + r;
            ull accA[16], accB[16];
#pragma unroll
            for (int b = 0; b < 16; b++) { accA[b] = 0ull; accB[b] = 0ull; }
            gtileQ(out_w, HH, rowbase, 0, 0, 16, xs, 512, accA, accB);
            float biasA = out_b[rowA], biasB = out_b[rowB];
            ull my = 0ull;
#pragma unroll
            for (int b = 0; b < 16; b++) {
                float sA = kqsum(accA[b]) + biasA;
                float sB = kqsum(accB[b]) + biasB;
                unsigned uA = __float_as_uint(sA);
                uA = (uA & 0x80000000u) ? ~uA : (uA | 0x80000000u);
                unsigned uB = __float_as_uint(sB);
                uB = (uB & 0x80000000u) ? ~uB : (uB | 0x80000000u);
                ull kA = ((ull)uA << 32) | (ull)(0xFFFFFFFFu - (unsigned)rowA);
                ull kB = ((ull)uB << 32) | (ull)(0xFFFFFFFFu - (unsigned)rowB);
                ull key = (kB > kA) ? kB : kA;
#pragma unroll
                for (int off = 8; off <= 16; off <<= 1) {  // max over the r quads
                    ull o2 = __shfl_xor_sync(0xffffffffu, key, off);
                    if (o2 > key) key = o2;
                }
                if (lane == b) my = key;                   // lane b keeps batch b
            }
            if (lane < 16 && my) atomicMax(&sbest[lane], my);
        }
        __syncthreads();
        if (tid < 16) atomicMax(&g_amax[t][tid], sbest[tid]);
        gsync();
    }

    // ---- finalize: out[b,t,:] = transfer_w[argmax] for t<128, else sentences ----
    for (int i = blk * NTH + tid; i < BB * TT * (EE / 4); i += GRID * NTH) {
        int k4 = (i & 127) * 4;
        int bt = i >> 7;
        int b = bt / TT, tt = bt - b * TT;
        float4 v;
        if (tt < SS) {
            int idx = (int)(0xFFFFFFFFu - (unsigned)(g_amax[tt][b] & 0xFFFFFFFFull));
            v = *(const float4*)(transfer_w + (size_t)idx * EE + k4);
        } else {
            v = *(const float4*)(sentences + (size_t)bt * EE + k4);
        }
        *(float4*)(out + (size_t)bt * EE + k4) = v;
    }
}

// ---------------------------------------------------------------------------
extern "C" void kernel_launch(void* const* d_in, const int* in_sizes, int n_in,
                              void* d_out, int out_size) {
    const float* hiddens    = (const float*)d_in[0];
    const float* sentences  = (const float*)d_in[1];
    const int*   relations  = (const int*)d_in[2];
    const int*   gold       = (const int*)d_in[3];
    const unsigned char* tmask = (const unsigned char*)d_in[4];
    const float* embed      = (const float*)d_in[5];
    const float* rel_emb    = (const float*)d_in[6];
    const float* w_ih0      = (const float*)d_in[7];
    const float* w_hh0      = (const float*)d_in[8];
    const float* b0         = (const float*)d_in[9];
    const float* w_ih1      = (const float*)d_in[10];
    const float* w_hh1      = (const float*)d_in[11];
    const float* b1         = (const float*)d_in[12];
    const float* out_w      = (const float*)d_in[13];
    const float* out_b      = (const float*)d_in[14];
    const float* transfer_w = (const float*)d_in[15];

    const int smem = BB * 1152 * sizeof(float);   // 73728 B dynamic
    cudaFuncSetAttribute(seq_kernel, cudaFuncAttributeMaxDynamicSharedMemorySize, smem);

    init_kernel<<<1, 1024>>>(hiddens, tmask);
    seq_kernel<<<GRID, NTH, smem>>>(sentences, relations, gold, tmask, embed, rel_emb,
                                    w_ih0, w_hh0, b0, w_ih1, w_hh1, b1,
                                    out_w, out_b, transfer_w, (float*)d_out);
}